// round 1
// baseline (speedup 1.0000x reference)
#include <cuda_runtime.h>
#include <math.h>

#define N_NODES   100000
#define DEG       16
#define IN_DIM    128
#define OUT_DIM   32
#define EPS       1e-8f

// scratch (device globals: no allocation allowed in kernel_launch)
__device__ float g_z[N_NODES * OUT_DIM];
__device__ float g_norms[N_NODES];

// ---------------------------------------------------------------------------
// Kernel 1: z = h @ W^T  fused with row norms (clamped to EPS).
// Block tile: 64 rows x 32 cols, 128 threads, 4x4 per thread.
// SMEM: h tile as float4 with XOR swizzle (32KB) + W transposed (16KB) = 48KB.
// ---------------------------------------------------------------------------
__global__ __launch_bounds__(128) void gemm_norm_kernel(
    const float* __restrict__ h, const float* __restrict__ W, int N)
{
    __shared__ float4 hs4[32][64];     // hs4[k4][row^ (k4&7)] = h[row][4k4..4k4+3]
    __shared__ float  Wt[128][32];     // Wt[k][d] = W[d][k]

    const int tid  = threadIdx.x;
    const int row0 = blockIdx.x * 64;

    // --- load W transposed: thread -> d = c&31 (conflict-free STS) ---
    #pragma unroll
    for (int i = 0; i < 32; i++) {
        int c = tid + i * 128;         // 0..4095
        int d = c & 31;
        int k = c >> 5;
        Wt[k][d] = W[d * IN_DIM + k];
    }

    // --- load h tile (coalesced LDG.128), swizzled STS ---
    const float4* h4 = reinterpret_cast<const float4*>(h);
    #pragma unroll
    for (int i = 0; i < 16; i++) {
        int c   = tid + i * 128;       // 0..2047
        int row = c >> 5;              // 0..63
        int k4  = c & 31;              // 0..31
        int grow = row0 + row;
        float4 val = make_float4(0.f, 0.f, 0.f, 0.f);
        if (grow < N) val = h4[grow * 32 + k4];
        hs4[k4][row ^ (k4 & 7)] = val;
    }
    __syncthreads();

    const int rg  = tid >> 3;          // 0..15 -> rows 4*rg..4*rg+3
    const int cg  = tid & 7;           // 0..7  -> cols 4*cg..4*cg+3
    const int rg4 = rg * 4;
    const int cg4 = cg * 4;

    float acc[4][4];
    #pragma unroll
    for (int r = 0; r < 4; r++)
        #pragma unroll
        for (int c = 0; c < 4; c++) acc[r][c] = 0.f;

    #pragma unroll 4
    for (int k4 = 0; k4 < 32; k4++) {
        int sw = k4 & 7;
        float4 w0 = *reinterpret_cast<const float4*>(&Wt[4 * k4 + 0][cg4]);
        float4 w1 = *reinterpret_cast<const float4*>(&Wt[4 * k4 + 1][cg4]);
        float4 w2 = *reinterpret_cast<const float4*>(&Wt[4 * k4 + 2][cg4]);
        float4 w3 = *reinterpret_cast<const float4*>(&Wt[4 * k4 + 3][cg4]);
        #pragma unroll
        for (int r = 0; r < 4; r++) {
            float4 hr = hs4[k4][(rg4 + r) ^ sw];
            acc[r][0] += hr.x * w0.x; acc[r][1] += hr.x * w0.y;
            acc[r][2] += hr.x * w0.z; acc[r][3] += hr.x * w0.w;
            acc[r][0] += hr.y * w1.x; acc[r][1] += hr.y * w1.y;
            acc[r][2] += hr.y * w1.z; acc[r][3] += hr.y * w1.w;
            acc[r][0] += hr.z * w2.x; acc[r][1] += hr.z * w2.y;
            acc[r][2] += hr.z * w2.z; acc[r][3] += hr.z * w2.w;
            acc[r][0] += hr.w * w3.x; acc[r][1] += hr.w * w3.y;
            acc[r][2] += hr.w * w3.z; acc[r][3] += hr.w * w3.w;
        }
    }

    // --- epilogue: store z + row norms (reduce sum-of-squares across cg) ---
    #pragma unroll
    for (int r = 0; r < 4; r++) {
        int grow = row0 + rg4 + r;
        float ss = acc[r][0] * acc[r][0] + acc[r][1] * acc[r][1]
                 + acc[r][2] * acc[r][2] + acc[r][3] * acc[r][3];
        ss += __shfl_xor_sync(0xffffffffu, ss, 1);
        ss += __shfl_xor_sync(0xffffffffu, ss, 2);
        ss += __shfl_xor_sync(0xffffffffu, ss, 4);
        if (grow < N) {
            *reinterpret_cast<float4*>(&g_z[grow * OUT_DIM + cg4]) =
                make_float4(acc[r][0], acc[r][1], acc[r][2], acc[r][3]);
            if (cg == 0)
                g_norms[grow] = fmaxf(sqrtf(ss), EPS);
        }
    }
}

// ---------------------------------------------------------------------------
// Kernel 2: per-node cosine attention + softmax + weighted aggregation.
// One warp per node (dst = e/16, edges contiguous). lane = output dim.
// ---------------------------------------------------------------------------
__global__ __launch_bounds__(256) void edge_agg_kernel(
    const float* __restrict__ beta_p, const int* __restrict__ src,
    float* __restrict__ out, int N)
{
    const int warp_id = (blockIdx.x * blockDim.x + threadIdx.x) >> 5;
    const int lane    = threadIdx.x & 31;
    if (warp_id >= N) return;
    const int node = warp_id;

    const float beta = beta_p[0];
    const float zdl  = g_z[node * OUT_DIM + lane];
    const float nd   = g_norms[node];

    int   sidx   = 0;
    float ns_own = 1.f;
    if (lane < DEG) {
        sidx   = src[node * DEG + lane];
        ns_own = g_norms[sidx];
    }

    // gather src feature rows (coalesced per edge, z is L2-resident)
    float v[DEG];
    #pragma unroll
    for (int e = 0; e < DEG; e++) {
        int idx = __shfl_sync(0xffffffffu, sidx, e);
        v[e] = g_z[idx * OUT_DIM + lane];
    }

    // per-edge scores: dot via warp reduction, cosine, -beta*(1-cos)
    float sc[DEG];
    #pragma unroll
    for (int e = 0; e < DEG; e++) {
        float p = v[e] * zdl;
        p += __shfl_xor_sync(0xffffffffu, p, 16);
        p += __shfl_xor_sync(0xffffffffu, p, 8);
        p += __shfl_xor_sync(0xffffffffu, p, 4);
        p += __shfl_xor_sync(0xffffffffu, p, 2);
        p += __shfl_xor_sync(0xffffffffu, p, 1);
        float ns  = __shfl_sync(0xffffffffu, ns_own, e);
        float cosv = __fdividef(p, ns * nd);
        sc[e] = -beta * (1.0f - cosv);
    }

    // softmax over the 16 edges (all lanes hold all scores -> no comms needed)
    float m = sc[0];
    #pragma unroll
    for (int e = 1; e < DEG; e++) m = fmaxf(m, sc[e]);
    float denom = 0.f;
    #pragma unroll
    for (int e = 0; e < DEG; e++) {
        sc[e] = __expf(sc[e] - m);
        denom += sc[e];
    }

    float o = 0.f;
    #pragma unroll
    for (int e = 0; e < DEG; e++) o += sc[e] * v[e];

    out[node * OUT_DIM + lane] = __fdividef(o, denom);
}

extern "C" void kernel_launch(void* const* d_in, const int* in_sizes, int n_in,
                              void* d_out, int out_size)
{
    const float* h    = (const float*)d_in[0];   // [N, 128]
    const float* W    = (const float*)d_in[1];   // [32, 128]
    const float* beta = (const float*)d_in[2];   // [1]
    const int*   src  = (const int*)d_in[3];     // [E]
    // d_in[4] = dst, structurally arange(E)//16 -> implicit
    float* out = (float*)d_out;

    int N = in_sizes[0] / IN_DIM;                // 100000

    gemm_norm_kernel<<<(N + 63) / 64, 128>>>(h, W, N);
    edge_agg_kernel<<<(N + 7) / 8, 256>>>(beta, src, out, N);
}

// round 2
// speedup vs baseline: 1.1545x; 1.1545x over previous
#include <cuda_runtime.h>
#include <math.h>

#define N_NODES   100000
#define DEG       16
#define IN_DIM    128
#define OUT_DIM   32
#define EPS       1e-8f

// scratch (device globals: no allocation allowed in kernel_launch)
__device__ float g_z[N_NODES * OUT_DIM];
__device__ float g_inorm[N_NODES];          // 1 / max(||z_i||, EPS)

// ---------------------------------------------------------------------------
// Kernel 1: z = h @ W^T  fused with inverse row norms.
// Block tile: 64 rows x 32 cols, 128 threads, 4x4 per thread.
// SMEM: h tile as float4 with XOR swizzle (32KB) + W transposed (16KB) = 48KB.
// ---------------------------------------------------------------------------
__global__ __launch_bounds__(128) void gemm_norm_kernel(
    const float* __restrict__ h, const float* __restrict__ W, int N)
{
    __shared__ float4 hs4[32][64];     // hs4[k4][row ^ (k4&7)] = h[row][4k4..4k4+3]
    __shared__ float  Wt[128][32];     // Wt[k][d] = W[d][k]

    const int tid  = threadIdx.x;
    const int row0 = blockIdx.x * 64;

    // --- load W transposed ---
    #pragma unroll
    for (int i = 0; i < 32; i++) {
        int c = tid + i * 128;         // 0..4095
        int d = c & 31;
        int k = c >> 5;
        Wt[k][d] = W[d * IN_DIM + k];
    }

    // --- load h tile (coalesced LDG.128), swizzled STS ---
    const float4* h4 = reinterpret_cast<const float4*>(h);
    #pragma unroll
    for (int i = 0; i < 16; i++) {
        int c   = tid + i * 128;       // 0..2047
        int row = c >> 5;              // 0..63
        int k4  = c & 31;              // 0..31
        int grow = row0 + row;
        float4 val = make_float4(0.f, 0.f, 0.f, 0.f);
        if (grow < N) val = h4[grow * 32 + k4];
        hs4[k4][row ^ (k4 & 7)] = val;
    }
    __syncthreads();

    const int rg  = tid >> 3;          // 0..15 -> rows 4*rg..4*rg+3
    const int cg  = tid & 7;           // 0..7  -> cols 4*cg..4*cg+3
    const int rg4 = rg * 4;
    const int cg4 = cg * 4;

    float acc[4][4];
    #pragma unroll
    for (int r = 0; r < 4; r++)
        #pragma unroll
        for (int c = 0; c < 4; c++) acc[r][c] = 0.f;

    #pragma unroll 4
    for (int k4 = 0; k4 < 32; k4++) {
        int sw = k4 & 7;
        float4 w0 = *reinterpret_cast<const float4*>(&Wt[4 * k4 + 0][cg4]);
        float4 w1 = *reinterpret_cast<const float4*>(&Wt[4 * k4 + 1][cg4]);
        float4 w2 = *reinterpret_cast<const float4*>(&Wt[4 * k4 + 2][cg4]);
        float4 w3 = *reinterpret_cast<const float4*>(&Wt[4 * k4 + 3][cg4]);
        #pragma unroll
        for (int r = 0; r < 4; r++) {
            float4 hr = hs4[k4][(rg4 + r) ^ sw];
            acc[r][0] += hr.x * w0.x; acc[r][1] += hr.x * w0.y;
            acc[r][2] += hr.x * w0.z; acc[r][3] += hr.x * w0.w;
            acc[r][0] += hr.y * w1.x; acc[r][1] += hr.y * w1.y;
            acc[r][2] += hr.y * w1.z; acc[r][3] += hr.y * w1.w;
            acc[r][0] += hr.z * w2.x; acc[r][1] += hr.z * w2.y;
            acc[r][2] += hr.z * w2.z; acc[r][3] += hr.z * w2.w;
            acc[r][0] += hr.w * w3.x; acc[r][1] += hr.w * w3.y;
            acc[r][2] += hr.w * w3.z; acc[r][3] += hr.w * w3.w;
        }
    }

    // --- epilogue: store z + inverse row norms ---
    #pragma unroll
    for (int r = 0; r < 4; r++) {
        int grow = row0 + rg4 + r;
        float ss = acc[r][0] * acc[r][0] + acc[r][1] * acc[r][1]
                 + acc[r][2] * acc[r][2] + acc[r][3] * acc[r][3];
        ss += __shfl_xor_sync(0xffffffffu, ss, 1);
        ss += __shfl_xor_sync(0xffffffffu, ss, 2);
        ss += __shfl_xor_sync(0xffffffffu, ss, 4);
        if (grow < N) {
            *reinterpret_cast<float4*>(&g_z[grow * OUT_DIM + cg4]) =
                make_float4(acc[r][0], acc[r][1], acc[r][2], acc[r][3]);
            if (cg == 0)
                g_inorm[grow] = 1.0f / fmaxf(sqrtf(ss), EPS);
        }
    }
}

// ---------------------------------------------------------------------------
// Kernel 2: per-node cosine attention + softmax + weighted aggregation.
// One warp per node, lane = output dim.
// Dot products via a shared hierarchical multi-reduction:
//   16 independent 32-lane reductions in 31 shfls (vs 80 naive), by packing
//   two edges into one register after each butterfly level.
// After the tree, lane l holds the full dot of edge
//   e(l) = bit4(l) | bit3(l)<<1 | bit2(l)<<2 | bit1(l)<<3
// so exp is computed once per edge, softmax max/sum are plain 5-shfl
// butterflies (each edge appears in exactly 2 lanes -> denom = sum/2).
// ---------------------------------------------------------------------------
__global__ __launch_bounds__(256) void edge_agg_kernel(
    const float* __restrict__ beta_p, const int* __restrict__ src,
    float* __restrict__ out, int N)
{
    const int warp_id = (blockIdx.x * blockDim.x + threadIdx.x) >> 5;
    const int lane    = threadIdx.x & 31;
    if (warp_id >= N) return;
    const int node = warp_id;

    const float beta   = __ldg(beta_p);
    const float zdl    = g_z[node * OUT_DIM + lane];
    const float inv_nd = g_inorm[node];

    // uniform src indices: 4 broadcast int4 loads (no shfl)
    const int4* src4 = reinterpret_cast<const int4*>(src + node * DEG);
    int4 s0 = __ldg(src4 + 0);
    int4 s1 = __ldg(src4 + 1);
    int4 s2 = __ldg(src4 + 2);
    int4 s3 = __ldg(src4 + 3);
    int si[DEG] = { s0.x, s0.y, s0.z, s0.w,  s1.x, s1.y, s1.z, s1.w,
                    s2.x, s2.y, s2.z, s2.w,  s3.x, s3.y, s3.z, s3.w };

    // per-edge inverse-norm scale (uniform scattered loads, issued early)
    float cc[DEG];
    #pragma unroll
    for (int e = 0; e < DEG; e++)
        cc[e] = __ldg(&g_inorm[si[e]]) * inv_nd;

    // gather src feature rows (coalesced 128B per edge, L2-resident)
    float v[DEG];
    #pragma unroll
    for (int e = 0; e < DEG; e++)
        v[e] = g_z[si[e] * OUT_DIM + lane];

    const unsigned FULL = 0xffffffffu;

    // ---- hierarchical multi-reduce: 16 dots in 31 shfls ----
    const bool b16 = (lane & 16) != 0;
    const bool b8  = (lane & 8)  != 0;
    const bool b4  = (lane & 4)  != 0;
    const bool b2  = (lane & 2)  != 0;

    float s[8];
    #pragma unroll
    for (int i = 0; i < 8; i++) {
        float p0 = v[2 * i]     * zdl * cc[2 * i];
        float p1 = v[2 * i + 1] * zdl * cc[2 * i + 1];
        float a = p0 + __shfl_xor_sync(FULL, p0, 16);
        float b = p1 + __shfl_xor_sync(FULL, p1, 16);
        s[i] = b16 ? b : a;
    }
    float q[4];
    #pragma unroll
    for (int i = 0; i < 4; i++) {
        float a = s[2 * i]     + __shfl_xor_sync(FULL, s[2 * i], 8);
        float b = s[2 * i + 1] + __shfl_xor_sync(FULL, s[2 * i + 1], 8);
        q[i] = b8 ? b : a;
    }
    float w[2];
    #pragma unroll
    for (int i = 0; i < 2; i++) {
        float a = q[2 * i]     + __shfl_xor_sync(FULL, q[2 * i], 4);
        float b = q[2 * i + 1] + __shfl_xor_sync(FULL, q[2 * i + 1], 4);
        w[i] = b4 ? b : a;
    }
    float xa = w[0] + __shfl_xor_sync(FULL, w[0], 2);
    float xb = w[1] + __shfl_xor_sync(FULL, w[1], 2);
    float x  = b2 ? xb : xa;
    float dotv = x + __shfl_xor_sync(FULL, x, 1);   // cos of edge e(lane)

    // score = -beta * (1 - cos) = beta*cos - beta
    float sc = fmaf(beta, dotv, -beta);

    // softmax over 16 edges (each lives in exactly 2 lanes)
    float m = sc;
    m = fmaxf(m, __shfl_xor_sync(FULL, m, 16));
    m = fmaxf(m, __shfl_xor_sync(FULL, m, 8));
    m = fmaxf(m, __shfl_xor_sync(FULL, m, 4));
    m = fmaxf(m, __shfl_xor_sync(FULL, m, 2));
    m = fmaxf(m, __shfl_xor_sync(FULL, m, 1));

    float esc = __expf(sc - m);                     // 1 exp per lane
    float ds  = esc;
    ds += __shfl_xor_sync(FULL, ds, 16);
    ds += __shfl_xor_sync(FULL, ds, 8);
    ds += __shfl_xor_sync(FULL, ds, 4);
    ds += __shfl_xor_sync(FULL, ds, 2);
    ds += __shfl_xor_sync(FULL, ds, 1);
    float denom = ds * 0.5f;                        // every edge counted twice

    // weighted aggregation: broadcast esc from the lane owning each edge
    float o = 0.f;
    #pragma unroll
    for (int e = 0; e < DEG; e++) {
        // lane holding edge e: bit4=e0, bit3=e1, bit2=e2, bit1=e3, bit0=0
        int srclane = ((e & 1) << 4) | ((e & 2) << 2) | (e & 4) | ((e & 8) >> 2);
        float a = __shfl_sync(FULL, esc, srclane);
        o = fmaf(a, v[e], o);
    }

    out[node * OUT_DIM + lane] = o / denom;
}

extern "C" void kernel_launch(void* const* d_in, const int* in_sizes, int n_in,
                              void* d_out, int out_size)
{
    const float* h    = (const float*)d_in[0];   // [N, 128]
    const float* W    = (const float*)d_in[1];   // [32, 128]
    const float* beta = (const float*)d_in[2];   // [1]
    const int*   src  = (const int*)d_in[3];     // [E]
    // d_in[4] = dst, structurally arange(E)//16 -> implicit
    float* out = (float*)d_out;

    int N = in_sizes[0] / IN_DIM;                // 100000

    gemm_norm_kernel<<<(N + 63) / 64, 128>>>(h, W, N);
    edge_agg_kernel<<<(N + 7) / 8, 256>>>(beta, src, out, N);
}

// round 3
// speedup vs baseline: 1.7607x; 1.5251x over previous
#include <cuda_runtime.h>
#include <math.h>
#include <stdint.h>

#define N_NODES   100000
#define DEG       16
#define IN_DIM    128
#define OUT_DIM   32
#define EPS       1e-8f

// scratch (device globals: no allocation allowed in kernel_launch)
__device__ float g_z[N_NODES * OUT_DIM];
__device__ float g_inorm[N_NODES];          // 1 / max(||z_i||, EPS)

// ---------------------------------------------------------------------------
// cp.async helpers
// ---------------------------------------------------------------------------
__device__ __forceinline__ void cp_async16(uint32_t smem_addr, const void* gptr) {
    asm volatile("cp.async.ca.shared.global [%0], [%1], 16;\n"
                 :: "r"(smem_addr), "l"(gptr));
}
__device__ __forceinline__ void cp_async_commit() {
    asm volatile("cp.async.commit_group;\n" ::: "memory");
}
template <int n>
__device__ __forceinline__ void cp_async_wait() {
    asm volatile("cp.async.wait_group %0;\n" :: "n"(n) : "memory");
}

// ---------------------------------------------------------------------------
// Kernel 1: z = h @ W^T  fused with inverse row norms.
// Persistent blocks, double-buffered 64-row h tiles via cp.async.
// Dynamic smem: 2 x 32KB h tile + 16KB W^T = 80KB. 2 blocks/SM.
// ---------------------------------------------------------------------------
__device__ __forceinline__ void prefetch_tile(
    const float4* __restrict__ h4, float4 (*hbuf)[64], int tile, int tid, int N)
{
    int row0 = tile * 64;
    #pragma unroll
    for (int i = 0; i < 16; i++) {
        int c   = tid + i * 128;       // 0..2047
        int row = c >> 5;              // 0..63
        int k4  = c & 31;              // 0..31
        int grow = row0 + row;
        if (grow >= N) grow = N - 1;   // clamp (results discarded in epilogue)
        uint32_t dst = (uint32_t)__cvta_generic_to_shared(&hbuf[k4][row ^ (k4 & 7)]);
        cp_async16(dst, h4 + grow * 32 + k4);
    }
}

__global__ __launch_bounds__(128) void gemm_norm_kernel(
    const float* __restrict__ h, const float* __restrict__ W, int N, int ntiles)
{
    extern __shared__ char smem_raw[];
    float4 (*hs4)[32][64] = reinterpret_cast<float4(*)[32][64]>(smem_raw);   // 2 x 32KB
    float  (*Wt)[32]      = reinterpret_cast<float(*)[32]>(smem_raw + 65536); // 16KB

    const int tid = threadIdx.x;
    const float4* h4 = reinterpret_cast<const float4*>(h);

    // --- load W transposed (once per block) ---
    #pragma unroll
    for (int i = 0; i < 32; i++) {
        int c = tid + i * 128;         // 0..4095
        int d = c & 31;
        int k = c >> 5;
        Wt[k][d] = W[d * IN_DIM + k];
    }

    const int stride = gridDim.x;
    const int t0 = blockIdx.x;

    if (t0 < ntiles) prefetch_tile(h4, hs4[0], t0, tid, N);
    cp_async_commit();

    const int rg  = tid >> 3;          // 0..15
    const int cg  = tid & 7;           // 0..7
    const int rg4 = rg * 4;
    const int cg4 = cg * 4;

    int cur = 0;
    for (int t = t0; t < ntiles; t += stride) {
        int nt = t + stride;
        if (nt < ntiles) prefetch_tile(h4, hs4[cur ^ 1], nt, tid, N);
        cp_async_commit();
        cp_async_wait<1>();            // buffer `cur` ready
        __syncthreads();

        float4 (*hb)[64] = hs4[cur];

        float acc[4][4];
        #pragma unroll
        for (int r = 0; r < 4; r++)
            #pragma unroll
            for (int c = 0; c < 4; c++) acc[r][c] = 0.f;

        #pragma unroll 4
        for (int k4 = 0; k4 < 32; k4++) {
            int sw = k4 & 7;
            float4 w0 = *reinterpret_cast<const float4*>(&Wt[4 * k4 + 0][cg4]);
            float4 w1 = *reinterpret_cast<const float4*>(&Wt[4 * k4 + 1][cg4]);
            float4 w2 = *reinterpret_cast<const float4*>(&Wt[4 * k4 + 2][cg4]);
            float4 w3 = *reinterpret_cast<const float4*>(&Wt[4 * k4 + 3][cg4]);
            #pragma unroll
            for (int r = 0; r < 4; r++) {
                float4 hr = hb[k4][(rg4 + r) ^ sw];
                acc[r][0] += hr.x * w0.x; acc[r][1] += hr.x * w0.y;
                acc[r][2] += hr.x * w0.z; acc[r][3] += hr.x * w0.w;
                acc[r][0] += hr.y * w1.x; acc[r][1] += hr.y * w1.y;
                acc[r][2] += hr.y * w1.z; acc[r][3] += hr.y * w1.w;
                acc[r][0] += hr.z * w2.x; acc[r][1] += hr.z * w2.y;
                acc[r][2] += hr.z * w2.z; acc[r][3] += hr.z * w2.w;
                acc[r][0] += hr.w * w3.x; acc[r][1] += hr.w * w3.y;
                acc[r][2] += hr.w * w3.z; acc[r][3] += hr.w * w3.w;
            }
        }

        // epilogue: store z + inverse row norms
        int row0 = t * 64;
        #pragma unroll
        for (int r = 0; r < 4; r++) {
            int grow = row0 + rg4 + r;
            float ss = acc[r][0] * acc[r][0] + acc[r][1] * acc[r][1]
                     + acc[r][2] * acc[r][2] + acc[r][3] * acc[r][3];
            ss += __shfl_xor_sync(0xffffffffu, ss, 1);
            ss += __shfl_xor_sync(0xffffffffu, ss, 2);
            ss += __shfl_xor_sync(0xffffffffu, ss, 4);
            if (grow < N) {
                *reinterpret_cast<float4*>(&g_z[grow * OUT_DIM + cg4]) =
                    make_float4(acc[r][0], acc[r][1], acc[r][2], acc[r][3]);
                if (cg == 0)
                    g_inorm[grow] = 1.0f / fmaxf(sqrtf(ss), EPS);
            }
        }
        __syncthreads();               // all done reading buf `cur` before reuse
        cur ^= 1;
    }
}

// ---------------------------------------------------------------------------
// Kernel 2: per-node cosine attention + softmax + weighted aggregation.
// HALF-WARP per node: lanes 0-15 -> node A, 16-31 -> node B; each lane owns
// 2 output dims (float2). 16 dots multi-reduced over 16 lanes in 30 shfl per
// WARP (covers both nodes). Edges are gathered in bit-reversed order so that
// after the tree, lane hl holds exactly edge hl's dot.
// ---------------------------------------------------------------------------
__global__ __launch_bounds__(256) void edge_agg_kernel(
    const float* __restrict__ beta_p, const int* __restrict__ src,
    float* __restrict__ out, int N)
{
    const int warp_id = (blockIdx.x * blockDim.x + threadIdx.x) >> 5;
    if (warp_id * 2 >= N) return;                 // uniform per warp

    const int lane = threadIdx.x & 31;
    const int half = lane >> 4;                   // 0 / 1
    const int hl   = lane & 15;
    int node = warp_id * 2 + half;
    const bool valid = (node < N);
    if (!valid) node = N - 1;

    const unsigned FULL = 0xffffffffu;
    const float beta = __ldg(beta_p);

    const float2 zd    = *reinterpret_cast<const float2*>(&g_z[node * OUT_DIM + 2 * hl]);
    const float inv_nd = g_inorm[node];

    // all 16 src indices of this node (2 distinct addresses per LDG.128)
    const int4* sp = reinterpret_cast<const int4*>(src + node * DEG);
    int4 s0 = __ldg(sp + 0);
    int4 s1 = __ldg(sp + 1);
    int4 s2 = __ldg(sp + 2);
    int4 s3 = __ldg(sp + 3);
    int si[DEG] = { s0.x, s0.y, s0.z, s0.w,  s1.x, s1.y, s1.z, s1.w,
                    s2.x, s2.y, s2.z, s2.w,  s3.x, s3.y, s3.z, s3.w };

    // own-edge src (coalesced) -> per-edge cosine scale, applied post-reduction
    const int sid_own = __ldg(src + node * DEG + hl);
    const float cc = __ldg(&g_inorm[sid_own]) * inv_nd;

    // 4-bit bit-reversal (involution): gather order so lane hl ends on edge hl
    constexpr int REV4[16] = {0,8,4,12, 2,10,6,14, 1,9,5,13, 3,11,7,15};

    // gather src feature rows (128B per edge per node, L2-resident)
    float2 v[DEG];
    #pragma unroll
    for (int k = 0; k < DEG; k++)
        v[k] = *reinterpret_cast<const float2*>(&g_z[si[REV4[k]] * OUT_DIM + 2 * hl]);

    // per-lane partial dots
    float p[DEG];
    #pragma unroll
    for (int k = 0; k < DEG; k++)
        p[k] = fmaf(v[k].x, zd.x, v[k].y * zd.y);

    // ---- hierarchical multi-reduce: 16 dots over 16 lanes, 30 shfl/warp ----
    const bool b8 = (hl & 8) != 0;
    const bool b4 = (hl & 4) != 0;
    const bool b2 = (hl & 2) != 0;
    const bool b1 = (hl & 1) != 0;

    float s[8];
    #pragma unroll
    for (int i = 0; i < 8; i++) {
        float a = p[2 * i]     + __shfl_xor_sync(FULL, p[2 * i], 8);
        float b = p[2 * i + 1] + __shfl_xor_sync(FULL, p[2 * i + 1], 8);
        s[i] = b8 ? b : a;
    }
    float q[4];
    #pragma unroll
    for (int i = 0; i < 4; i++) {
        float a = s[2 * i]     + __shfl_xor_sync(FULL, s[2 * i], 4);
        float b = s[2 * i + 1] + __shfl_xor_sync(FULL, s[2 * i + 1], 4);
        q[i] = b4 ? b : a;
    }
    float w2_[2];
    #pragma unroll
    for (int i = 0; i < 2; i++) {
        float a = q[2 * i]     + __shfl_xor_sync(FULL, q[2 * i], 2);
        float b = q[2 * i + 1] + __shfl_xor_sync(FULL, q[2 * i + 1], 2);
        w2_[i] = b2 ? b : a;
    }
    float xa = w2_[0] + __shfl_xor_sync(FULL, w2_[0], 1);
    float xb = w2_[1] + __shfl_xor_sync(FULL, w2_[1], 1);
    float dotv = b1 ? xb : xa;                    // raw dot of edge `hl`

    // score = -beta * (1 - cos)
    float sc = fmaf(beta, dotv * cc, -beta);

    // softmax over the 16 edges (one per lane, within half-warp)
    float m = sc;
    m = fmaxf(m, __shfl_xor_sync(FULL, m, 8));
    m = fmaxf(m, __shfl_xor_sync(FULL, m, 4));
    m = fmaxf(m, __shfl_xor_sync(FULL, m, 2));
    m = fmaxf(m, __shfl_xor_sync(FULL, m, 1));

    float esc = __expf(sc - m);
    float denom = esc;
    denom += __shfl_xor_sync(FULL, denom, 8);
    denom += __shfl_xor_sync(FULL, denom, 4);
    denom += __shfl_xor_sync(FULL, denom, 2);
    denom += __shfl_xor_sync(FULL, denom, 1);

    // weighted aggregation: esc for edge REV4[k] lives in lane (half*16 | REV4[k])
    float ox = 0.f, oy = 0.f;
    #pragma unroll
    for (int k = 0; k < DEG; k++) {
        float a = __shfl_sync(FULL, esc, (lane & 16) | REV4[k]);
        ox = fmaf(a, v[k].x, ox);
        oy = fmaf(a, v[k].y, oy);
    }

    if (valid) {
        float invd = 1.0f / denom;
        *reinterpret_cast<float2*>(&out[node * OUT_DIM + 2 * hl]) =
            make_float2(ox * invd, oy * invd);
    }
}

extern "C" void kernel_launch(void* const* d_in, const int* in_sizes, int n_in,
                              void* d_out, int out_size)
{
    const float* h    = (const float*)d_in[0];   // [N, 128]
    const float* W    = (const float*)d_in[1];   // [32, 128]
    const float* beta = (const float*)d_in[2];   // [1]
    const int*   src  = (const int*)d_in[3];     // [E]
    // d_in[4] = dst, structurally arange(E)//16 -> implicit
    float* out = (float*)d_out;

    int N = in_sizes[0] / IN_DIM;                // 100000
    int ntiles = (N + 63) / 64;

    const int GEMM_SMEM = 2 * 32768 + 16384;     // 80KB dynamic
    cudaFuncSetAttribute(gemm_norm_kernel,
                         cudaFuncAttributeMaxDynamicSharedMemorySize, GEMM_SMEM);

    int grid = 296;                               // 2 blocks/SM * 148 SMs
    if (grid > ntiles) grid = ntiles;
    gemm_norm_kernel<<<grid, 128, GEMM_SMEM>>>(h, W, N, ntiles);

    int nwarps  = (N + 1) / 2;
    int nblocks = (nwarps + 7) / 8;               // 8 warps / block
    edge_agg_kernel<<<nblocks, 256>>>(beta, src, out, N);
}

// round 5
// speedup vs baseline: 2.1083x; 1.1974x over previous
#include <cuda_runtime.h>
#include <mma.h>
#include <math.h>
#include <stdint.h>

using namespace nvcuda;

#define N_NODES   100000
#define DEG       16
#define IN_DIM    128
#define OUT_DIM   32
#define EPS       1e-8f

// scratch (device globals: no allocation allowed in kernel_launch)
__device__ float g_z[N_NODES * OUT_DIM];
__device__ float g_inorm[N_NODES];          // 1 / max(||z_i||, EPS)

__device__ __forceinline__ float f2tf32(float x) {
    float r;
    asm("cvt.rna.tf32.f32 %0, %1;" : "=f"(r) : "f"(x));
    return r;
}

// ---------------------------------------------------------------------------
// Kernel 1: z = h @ W^T via wmma TF32 (m16n16k8), fused inverse row norms.
// Persistent CTAs (2/SM), 128 threads = 4 warps.
// Warp w: rows (w&1)*32 .. +32 (two 16-row m-tiles), cols (w>>1)*16 (one n-tile).
// All 16 B fragments (W) preloaded into registers once per CTA.
// Dynamic smem layout (floats):
//   Ws  [32][132]   @ 0       (16896 B)
//   hs  [64][132]   @ 4224    (33792 B)
//   zsm [64][36]    @ 12672   ( 9216 B)   total 59904 B
// ---------------------------------------------------------------------------
#define LDH 132
#define LDZ 36
#define GEMM_SMEM_BYTES 59904

__global__ __launch_bounds__(128) void gemm_wmma_kernel(
    const float* __restrict__ h, const float* __restrict__ W, int N, int ntiles)
{
    extern __shared__ float sm[];
    float* Ws  = sm;            // [32][132]
    float* hs  = sm + 4224;     // [64][132]
    float* zsm = sm + 12672;    // [64][36]

    const int tid  = threadIdx.x;
    const int lane = tid & 31;
    const int wid  = tid >> 5;
    const int m0w  = (wid & 1) * 32;
    const int n0   = (wid >> 1) * 16;
    const unsigned FULL = 0xffffffffu;

    // ---- load W -> tf32-rounded smem (once per CTA) ----
    const float4* W4 = reinterpret_cast<const float4*>(W);
    #pragma unroll
    for (int i = 0; i < 8; i++) {
        int f  = tid + i * 128;            // float4 index 0..1023
        int n  = f >> 5;
        int k4 = f & 31;
        float4 v = __ldg(&W4[n * 32 + k4]);
        float* d = &Ws[n * LDH + k4 * 4];
        d[0] = f2tf32(v.x); d[1] = f2tf32(v.y);
        d[2] = f2tf32(v.z); d[3] = f2tf32(v.w);
    }
    __syncthreads();

    // ---- preload all 16 B fragments into registers ----
    wmma::fragment<wmma::matrix_b, 16, 16, 8, wmma::precision::tf32,
                   wmma::col_major> bfr[16];
    #pragma unroll
    for (int ks = 0; ks < 16; ks++)
        wmma::load_matrix_sync(bfr[ks], &Ws[n0 * LDH + ks * 8], LDH);

    const float4* h4 = reinterpret_cast<const float4*>(h);

    for (int t = blockIdx.x; t < ntiles; t += gridDim.x) {
        const int row0 = t * 64;
        __syncthreads();   // previous iteration fully done with hs/zsm

        // ---- load 64-row h tile -> tf32-rounded smem ----
        #pragma unroll
        for (int i = 0; i < 16; i++) {
            int f   = tid + i * 128;        // float4 index 0..2047
            int r   = f >> 5;               // 0..63
            int k4  = f & 31;               // 0..31
            int grow = row0 + r;
            if (grow >= N) grow = N - 1;
            float4 v = __ldg(&h4[grow * 32 + k4]);
            float* d = &hs[r * LDH + k4 * 4];
            d[0] = f2tf32(v.x); d[1] = f2tf32(v.y);
            d[2] = f2tf32(v.z); d[3] = f2tf32(v.w);
        }
        __syncthreads();

        // ---- wmma: 2 m-tiles x 16 k-steps ----
        wmma::fragment<wmma::accumulator, 16, 16, 8, float> c0, c1;
        wmma::fill_fragment(c0, 0.0f);
        wmma::fill_fragment(c1, 0.0f);
        wmma::fragment<wmma::matrix_a, 16, 16, 8, wmma::precision::tf32,
                       wmma::row_major> a0, a1;
        #pragma unroll
        for (int ks = 0; ks < 16; ks++) {
            wmma::load_matrix_sync(a0, &hs[m0w * LDH + ks * 8], LDH);
            wmma::load_matrix_sync(a1, &hs[(m0w + 16) * LDH + ks * 8], LDH);
            wmma::mma_sync(c0, a0, bfr[ks], c0);
            wmma::mma_sync(c1, a1, bfr[ks], c1);
        }
        wmma::store_matrix_sync(&zsm[m0w * LDZ + n0], c0, LDZ, wmma::mem_row_major);
        wmma::store_matrix_sync(&zsm[(m0w + 16) * LDZ + n0], c1, LDZ, wmma::mem_row_major);
        __syncthreads();

        // ---- epilogue: coalesced z write + inverse norms ----
        // thread t: row = t/2, col half = (t&1)*16
        int row  = tid >> 1;
        int colh = (tid & 1) * 16;
        float4 z4[4];
        float ss = 0.f;
        #pragma unroll
        for (int i = 0; i < 4; i++) {
            z4[i] = *reinterpret_cast<const float4*>(&zsm[row * LDZ + colh + i * 4]);
            ss += z4[i].x * z4[i].x + z4[i].y * z4[i].y
                + z4[i].z * z4[i].z + z4[i].w * z4[i].w;
        }
        ss += __shfl_xor_sync(FULL, ss, 1);
        int grow = row0 + row;
        if (grow < N) {
            float4* dst = reinterpret_cast<float4*>(&g_z[grow * OUT_DIM + colh]);
            #pragma unroll
            for (int i = 0; i < 4; i++) dst[i] = z4[i];
            if ((tid & 1) == 0)
                g_inorm[grow] = 1.0f / fmaxf(sqrtf(ss), EPS);
        }
    }
}

// ---------------------------------------------------------------------------
// Kernel 2: per-node cosine attention + softmax + weighted aggregation.
// Half-warp per node; hierarchical multi-reduce (30 shfl/warp for 32 dots).
// Softmax max-subtraction dropped (scores bounded in [-2,0]).
// esc broadcast via REV4-permuted smem row: 1 STS + 4 broadcast LDS.128.
// ---------------------------------------------------------------------------
__global__ __launch_bounds__(256) void edge_agg_kernel(
    const float* __restrict__ beta_p, const int* __restrict__ src,
    float* __restrict__ out, int N)
{
    __shared__ float alpha_sm[8][32];

    const int warp_id = (blockIdx.x * blockDim.x + threadIdx.x) >> 5;
    if (warp_id * 2 >= N) return;

    const int w    = threadIdx.x >> 5;
    const int lane = threadIdx.x & 31;
    const int half = lane >> 4;
    const int hl   = lane & 15;
    int node = warp_id * 2 + half;
    const bool valid = (node < N);
    if (!valid) node = N - 1;

    const unsigned FULL = 0xffffffffu;
    const float beta = __ldg(beta_p);

    const float2 zd    = *reinterpret_cast<const float2*>(&g_z[node * OUT_DIM + 2 * hl]);
    const float inv_nd = g_inorm[node];

    const int4* sp = reinterpret_cast<const int4*>(src + node * DEG);
    int4 s0 = __ldg(sp + 0);
    int4 s1 = __ldg(sp + 1);
    int4 s2 = __ldg(sp + 2);
    int4 s3 = __ldg(sp + 3);
    int si[DEG] = { s0.x, s0.y, s0.z, s0.w,  s1.x, s1.y, s1.z, s1.w,
                    s2.x, s2.y, s2.z, s2.w,  s3.x, s3.y, s3.z, s3.w };

    // own-edge src (coalesced) -> per-edge cosine scale
    const int sid_own = __ldg(src + node * DEG + hl);
    const float cc = __ldg(&g_inorm[sid_own]) * inv_nd;

    // 4-bit bit-reversal (involution): lane hl ends holding edge hl's dot
    constexpr int REV4[16] = {0,8,4,12, 2,10,6,14, 1,9,5,13, 3,11,7,15};

    float2 v[DEG];
    #pragma unroll
    for (int k = 0; k < DEG; k++)
        v[k] = *reinterpret_cast<const float2*>(&g_z[si[REV4[k]] * OUT_DIM + 2 * hl]);

    float p[DEG];
    #pragma unroll
    for (int k = 0; k < DEG; k++)
        p[k] = fmaf(v[k].x, zd.x, v[k].y * zd.y);

    const bool b8 = (hl & 8) != 0;
    const bool b4 = (hl & 4) != 0;
    const bool b2 = (hl & 2) != 0;
    const bool b1 = (hl & 1) != 0;

    float s[8];
    #pragma unroll
    for (int i = 0; i < 8; i++) {
        float a = p[2 * i]     + __shfl_xor_sync(FULL, p[2 * i], 8);
        float b = p[2 * i + 1] + __shfl_xor_sync(FULL, p[2 * i + 1], 8);
        s[i] = b8 ? b : a;
    }
    float q[4];
    #pragma unroll
    for (int i = 0; i < 4; i++) {
        float a = s[2 * i]     + __shfl_xor_sync(FULL, s[2 * i], 4);
        float b = s[2 * i + 1] + __shfl_xor_sync(FULL, s[2 * i + 1], 4);
        q[i] = b4 ? b : a;
    }
    float w2_[2];
    #pragma unroll
    for (int i = 0; i < 2; i++) {
        float a = q[2 * i]     + __shfl_xor_sync(FULL, q[2 * i], 2);
        float b = q[2 * i + 1] + __shfl_xor_sync(FULL, q[2 * i + 1], 2);
        w2_[i] = b2 ? b : a;
    }
    float xa = w2_[0] + __shfl_xor_sync(FULL, w2_[0], 1);
    float xb = w2_[1] + __shfl_xor_sync(FULL, w2_[1], 1);
    float dotv = b1 ? xb : xa;                 // raw dot of edge `hl`

    // score in [-2*beta, 0] -> exp safe without max subtraction
    float sc  = fmaf(beta, dotv * cc, -beta);
    float esc = __expf(sc);

    float denom = esc;
    denom += __shfl_xor_sync(FULL, denom, 8);
    denom += __shfl_xor_sync(FULL, denom, 4);
    denom += __shfl_xor_sync(FULL, denom, 2);
    denom += __shfl_xor_sync(FULL, denom, 1);

    // publish esc in REV4-permuted order: slot j holds esc of edge REV4[j],
    // so the aggregation loop reads sequentially (4 broadcast LDS.128).
    alpha_sm[w][(lane & 16) | REV4[hl]] = esc;
    __syncwarp(FULL);

    const float4* ap = reinterpret_cast<const float4*>(&alpha_sm[w][lane & 16]);
    float ox = 0.f, oy = 0.f;
    #pragma unroll
    for (int k4 = 0; k4 < 4; k4++) {
        float4 a4 = ap[k4];
        ox = fmaf(a4.x, v[4 * k4 + 0].x, ox);
        oy = fmaf(a4.x, v[4 * k4 + 0].y, oy);
        ox = fmaf(a4.y, v[4 * k4 + 1].x, ox);
        oy = fmaf(a4.y, v[4 * k4 + 1].y, oy);
        ox = fmaf(a4.z, v[4 * k4 + 2].x, ox);
        oy = fmaf(a4.z, v[4 * k4 + 2].y, oy);
        ox = fmaf(a4.w, v[4 * k4 + 3].x, ox);
        oy = fmaf(a4.w, v[4 * k4 + 3].y, oy);
    }

    if (valid) {
        float invd = 1.0f / denom;
        *reinterpret_cast<float2*>(&out[node * OUT_DIM + 2 * hl]) =
            make_float2(ox * invd, oy * invd);
    }
}

extern "C" void kernel_launch(void* const* d_in, const int* in_sizes, int n_in,
                              void* d_out, int out_size)
{
    const float* h    = (const float*)d_in[0];   // [N, 128]
    const float* W    = (const float*)d_in[1];   // [32, 128]
    const float* beta = (const float*)d_in[2];   // [1]
    const int*   src  = (const int*)d_in[3];     // [E]
    float* out = (float*)d_out;

    int N = in_sizes[0] / IN_DIM;                // 100000
    int ntiles = (N + 63) / 64;                  // 1563

    cudaFuncSetAttribute(gemm_wmma_kernel,
                         cudaFuncAttributeMaxDynamicSharedMemorySize,
                         GEMM_SMEM_BYTES);
    int grid = 296;                              // 2 CTAs/SM
    if (grid > ntiles) grid = ntiles;
    gemm_wmma_kernel<<<grid, 128, GEMM_SMEM_BYTES>>>(h, W, N, ntiles);

    int nwarps  = (N + 1) / 2;
    int nblocks = (nwarps + 7) / 8;              // 8 warps / block
    edge_agg_kernel<<<nblocks, 256>>>(beta, src, out, N);
}